// round 8
// baseline (speedup 1.0000x reference)
#include <cuda_runtime.h>
#include <cuda_fp16.h>
#include <math.h>
#include <stdint.h>

// Problem constants
#define S_LEN  2048
#define DMODEL 2048
#define HDIM   128
#define NH     16
#define NG     4
#define BATCH  2
#define KVLD   (NG * HDIM)   // 512

// Attention tiling: BQ=128 rows, 4 warps x 32 rows, K/V chunks of 64
#define BQ    128
#define BK    64
#define NJT   (S_LEN / BK)   // 32
#define QPH   160            // Q/K smem pitch in halves (320B; word pitch ≡16 mod 32)
#define VPH   96             // Vt pitch in halves
#define PPH   96             // P  pitch in halves
// smem offsets (halves)
#define OFF_QS   0
#define OFF_KS0  (BQ * QPH)                 // 20480
#define OFF_KS1  (OFF_KS0 + BK * QPH)       // 30720
#define OFF_VT0  (OFF_KS1 + BK * QPH)       // 40960
#define OFF_VT1  (OFF_VT0 + HDIM * VPH)     // 53248
#define OFF_PS   (OFF_VT1 + HDIM * VPH)     // 65536
#define ATTN_SMEM_HALVES (OFF_PS + BQ * PPH)
#define ATTN_SMEM_BYTES  (ATTN_SMEM_HALVES * 2)   // ~152 KB

// Projection tiling: 256(M) x 128(N), K-chunk 64 halves (two 32-half subs)
#define PTM   256
#define PTN   128
#define PTKC  64
#define POFF_A0  0
#define POFF_A1  (PTM * PTKC)
#define POFF_B0  (2 * PTM * PTKC)
#define POFF_B1  (2 * PTM * PTKC + PTN * PTKC)
#define PROJ_SMEM_HALVES (2 * PTM * PTKC + 2 * PTN * PTKC)
#define PROJ_SMEM_BYTES  (PROJ_SMEM_HALVES * 2)

// fp16 globals
__device__ __half g_kh[(size_t)BATCH * S_LEN * KVLD];             // [b][s][g*128+d]
__device__ __half g_vt[(size_t)BATCH * NG * HDIM * S_LEN];        // [b][g][d][s]
__device__ __half g_wh[(size_t)DMODEL * DMODEL];                  // [n][k]
__device__ __half g_attn[(size_t)BATCH * S_LEN * DMODEL];         // [m][k]

__device__ __forceinline__ float ex2(float x) {
    float r; asm("ex2.approx.f32 %0, %1;" : "=f"(r) : "f"(x)); return r;
}

__device__ __forceinline__ void mma_f16(float c[4],
    uint32_t a0, uint32_t a1, uint32_t a2, uint32_t a3, uint32_t b0, uint32_t b1)
{
    asm volatile(
        "mma.sync.aligned.m16n8k16.row.col.f32.f16.f16.f32 "
        "{%0,%1,%2,%3}, {%4,%5,%6,%7}, {%8,%9}, {%0,%1,%2,%3};"
        : "+f"(c[0]), "+f"(c[1]), "+f"(c[2]), "+f"(c[3])
        : "r"(a0), "r"(a1), "r"(a2), "r"(a3), "r"(b0), "r"(b1));
}

#define CP16(dst, src) asm volatile( \
    "cp.async.cg.shared.global [%0], [%1], 16;" :: "r"(dst), "l"(src))
#define CPCOMMIT() asm volatile("cp.async.commit_group;")
#define CPWAIT1()  asm volatile("cp.async.wait_group 1;")

// ---------------------------------------------------------------------------
// Pre-pass: f32 -> f16 flat convert (n % 4 == 0)
// ---------------------------------------------------------------------------
__global__ void conv_kernel(const float* __restrict__ src, __half* __restrict__ dst, int n)
{
    int i = (blockIdx.x * blockDim.x + threadIdx.x) * 4;
    if (i < n) {
        float4 t = *(const float4*)(src + i);
        *(__half2*)(dst + i)     = __floats2half2_rn(t.x, t.y);
        *(__half2*)(dst + i + 2) = __floats2half2_rn(t.z, t.w);
    }
}

// Pre-pass: V transpose  v[b][s][g*128+d] -> g_vt[b][g][d][s], fp16
__global__ void vtrans_kernel(const float* __restrict__ v)
{
    __shared__ float t[32][33];
    const int b = blockIdx.z >> 2, g = blockIdx.z & 3;
    const int d0 = blockIdx.y * 32, s0 = blockIdx.x * 32;
    const int tx = threadIdx.x, ty = threadIdx.y;
#pragma unroll
    for (int i = 0; i < 32; i += 8)
        t[ty + i][tx] = v[(size_t)(b * S_LEN + s0 + ty + i) * KVLD + g * HDIM + d0 + tx];
    __syncthreads();
#pragma unroll
    for (int i = 0; i < 32; i += 8)
        g_vt[((size_t)(b * NG + g) * HDIM + d0 + ty + i) * S_LEN + s0 + tx] =
            __float2half_rn(t[tx][ty + i]);
}

// ---------------------------------------------------------------------------
// Flash attention, fp16 m16n8k16, online softmax (base-2), cp.async pipeline.
// Grid: (S/BQ, NH, B). Block 128 = 4 warps; warp owns 32 Q rows (two 16-row
// mma pairs sharing every B fragment -> 1.73x less smem fragment traffic).
// k-permutation trick unchanged: A and B agree on the k ordering per uint4.
// ---------------------------------------------------------------------------
__global__ __launch_bounds__(128, 1)
void attn_kernel(const float* __restrict__ q)
{
    extern __shared__ __half sh[];
    const uint32_t sbase = (uint32_t)__cvta_generic_to_shared(sh);

    const int tid  = threadIdx.x;
    const int warp = tid >> 5;
    const int lane = tid & 31;
    const int gid  = lane >> 2;
    const int tig  = lane & 3;
    const int b  = blockIdx.z;
    const int h  = blockIdx.y;
    const int g  = h >> 2;
    const int s0 = blockIdx.x * BQ;
    const int wr = warp * 32;

    // scale * log2(e), folded into Q (softmax in base 2)
    const float scale = 0.08838834764831845f * 1.4426950408889634f;

    // Load + convert Q tile once (f32 -> f16, scaled)
    const float* qg = q + ((size_t)(b * S_LEN + s0)) * DMODEL + h * HDIM;
    for (int i = tid; i < BQ * (HDIM / 4); i += 128) {
        int r = i >> 5, c4 = (i & 31) << 2;
        float4 t = *(const float4*)(qg + (size_t)r * DMODEL + c4);
        __half* d = sh + OFF_QS + r * QPH + c4;
        *(__half2*)(d)     = __floats2half2_rn(t.x * scale, t.y * scale);
        *(__half2*)(d + 2) = __floats2half2_rn(t.z * scale, t.w * scale);
    }

    // cp.async source bases
    const __half* khb = g_kh + (size_t)b * S_LEN * KVLD + g * HDIM;
    const __half* vtb = g_vt + (size_t)(b * NG + g) * HDIM * S_LEN;

    // issue one tile's cp.asyncs into buffer p (128 threads, 8+8 chunks each)
    auto issue_tile = [&](int jt, int p) {
        const int kt0 = jt * BK;
        const uint32_t ksOff = sbase + (p ? OFF_KS1 : OFF_KS0) * 2;
        const uint32_t vtOff = sbase + (p ? OFF_VT1 : OFF_VT0) * 2;
#pragma unroll
        for (int u = 0; u < 8; u++) {
            int idx = tid + u * 128;
            int r = idx >> 4, c = idx & 15;                    // K: 64 rows x 16 chunks
            CP16(ksOff + (uint32_t)(r * QPH + c * 8) * 2,
                 khb + (size_t)(kt0 + r) * KVLD + c * 8);
        }
#pragma unroll
        for (int u = 0; u < 8; u++) {
            int idx = tid + u * 128;
            int d = idx >> 3, c = idx & 7;                     // V: 128 rows x 8 chunks
            CP16(vtOff + (uint32_t)(d * VPH + c * 8) * 2,
                 vtb + (size_t)d * S_LEN + kt0 + c * 8);
        }
    };

    issue_tile(0, 0);
    CPCOMMIT();

    // Accumulators: two 16-row pairs (pair 0: rows wr..wr+15, pair 1: +16)
    float Oc[2][16][4];
#pragma unroll
    for (int p = 0; p < 2; p++)
#pragma unroll
        for (int i = 0; i < 16; i++) {
            Oc[p][i][0] = Oc[p][i][1] = Oc[p][i][2] = Oc[p][i][3] = 0.f;
        }
    float mr[2][2] = { {-1e30f, -1e30f}, {-1e30f, -1e30f} };
    float lr[2][2] = { {0.f, 0.f}, {0.f, 0.f} };

    for (int jt = 0; jt < NJT; jt++) {
        const int p = jt & 1;
        if (jt + 1 < NJT) issue_tile(jt + 1, p ^ 1);
        CPCOMMIT();
        CPWAIT1();
        __syncthreads();   // tile jt ready for all warps

        const __half* Ks = sh + (p ? OFF_KS1 : OFF_KS0);
        const __half* Vt = sh + (p ? OFF_VT1 : OFF_VT0);
        __half* Ps = sh + OFF_PS;

        // ---- scores = Q @ K^T  (warp: 32 x 64), B shared across both pairs ----
        float sc[2][8][4];
#pragma unroll
        for (int pp = 0; pp < 2; pp++)
#pragma unroll
            for (int i = 0; i < 8; i++) {
                sc[pp][i][0] = sc[pp][i][1] = sc[pp][i][2] = sc[pp][i][3] = 0.f;
            }

#pragma unroll
        for (int bi = 0; bi < 4; bi++) {
            const int kk = bi * 32 + 8 * tig;
            uint4 A0 = *(const uint4*)(sh + OFF_QS + (wr + gid)      * QPH + kk);
            uint4 A1 = *(const uint4*)(sh + OFF_QS + (wr + gid + 8)  * QPH + kk);
            uint4 A2 = *(const uint4*)(sh + OFF_QS + (wr + gid + 16) * QPH + kk);
            uint4 A3 = *(const uint4*)(sh + OFF_QS + (wr + gid + 24) * QPH + kk);
#pragma unroll
            for (int nt = 0; nt < 8; nt++) {
                uint4 B = *(const uint4*)(Ks + (nt * 8 + gid) * QPH + kk);
                mma_f16(sc[0][nt], A0.x, A1.x, A0.y, A1.y, B.x, B.y);
                mma_f16(sc[0][nt], A0.z, A1.z, A0.w, A1.w, B.z, B.w);
                mma_f16(sc[1][nt], A2.x, A3.x, A2.y, A3.y, B.x, B.y);
                mma_f16(sc[1][nt], A2.z, A3.z, A2.w, A3.w, B.z, B.w);
            }
        }

        // ---- online softmax (base 2) per pair ----
#pragma unroll
        for (int pp = 0; pp < 2; pp++) {
            float mx0 = -1e30f, mx1 = -1e30f;
#pragma unroll
            for (int nt = 0; nt < 8; nt++) {
                mx0 = fmaxf(mx0, fmaxf(sc[pp][nt][0], sc[pp][nt][1]));
                mx1 = fmaxf(mx1, fmaxf(sc[pp][nt][2], sc[pp][nt][3]));
            }
            mx0 = fmaxf(mx0, __shfl_xor_sync(0xffffffffu, mx0, 1));
            mx0 = fmaxf(mx0, __shfl_xor_sync(0xffffffffu, mx0, 2));
            mx1 = fmaxf(mx1, __shfl_xor_sync(0xffffffffu, mx1, 1));
            mx1 = fmaxf(mx1, __shfl_xor_sync(0xffffffffu, mx1, 2));
            const float mn0 = fmaxf(mr[pp][0], mx0), mn1 = fmaxf(mr[pp][1], mx1);
            const float al0 = ex2(mr[pp][0] - mn0), al1 = ex2(mr[pp][1] - mn1);
            mr[pp][0] = mn0; mr[pp][1] = mn1;

            const int r0 = wr + pp * 16 + gid;
            float s0s = 0.f, s1s = 0.f;
#pragma unroll
            for (int nt = 0; nt < 8; nt++) {
                float p0 = ex2(sc[pp][nt][0] - mn0);
                float p1 = ex2(sc[pp][nt][1] - mn0);
                float p2 = ex2(sc[pp][nt][2] - mn1);
                float p3 = ex2(sc[pp][nt][3] - mn1);
                s0s += p0 + p1; s1s += p2 + p3;
                *(__half2*)(Ps + r0       * PPH + nt * 8 + 2 * tig) = __floats2half2_rn(p0, p1);
                *(__half2*)(Ps + (r0 + 8) * PPH + nt * 8 + 2 * tig) = __floats2half2_rn(p2, p3);
            }
            s0s += __shfl_xor_sync(0xffffffffu, s0s, 1);
            s0s += __shfl_xor_sync(0xffffffffu, s0s, 2);
            s1s += __shfl_xor_sync(0xffffffffu, s1s, 1);
            s1s += __shfl_xor_sync(0xffffffffu, s1s, 2);
            lr[pp][0] = lr[pp][0] * al0 + s0s;
            lr[pp][1] = lr[pp][1] * al1 + s1s;

#pragma unroll
            for (int nt = 0; nt < 16; nt++) {
                Oc[pp][nt][0] *= al0; Oc[pp][nt][1] *= al0;
                Oc[pp][nt][2] *= al1; Oc[pp][nt][3] *= al1;
            }
        }
        __syncwarp();   // Ps rows are warp-private

        // ---- O += P @ V  (warp: 32 x 128), B shared across both pairs ----
#pragma unroll
        for (int bi = 0; bi < 2; bi++) {
            const int kk = bi * 32 + 8 * tig;
            uint4 A0 = *(const uint4*)(Ps + (wr + gid)      * PPH + kk);
            uint4 A1 = *(const uint4*)(Ps + (wr + gid + 8)  * PPH + kk);
            uint4 A2 = *(const uint4*)(Ps + (wr + gid + 16) * PPH + kk);
            uint4 A3 = *(const uint4*)(Ps + (wr + gid + 24) * PPH + kk);
#pragma unroll
            for (int nt = 0; nt < 16; nt++) {
                uint4 B = *(const uint4*)(Vt + (nt * 8 + gid) * VPH + kk);
                mma_f16(Oc[0][nt], A0.x, A1.x, A0.y, A1.y, B.x, B.y);
                mma_f16(Oc[0][nt], A0.z, A1.z, A0.w, A1.w, B.z, B.w);
                mma_f16(Oc[1][nt], A2.x, A3.x, A2.y, A3.y, B.x, B.y);
                mma_f16(Oc[1][nt], A2.z, A3.z, A2.w, A3.w, B.z, B.w);
            }
        }
        __syncthreads();   // all warps done with buffer p before refill
    }

    // Epilogue: normalize, convert to fp16, store to g_attn
    __half* og = g_attn + (size_t)(b * S_LEN + s0) * DMODEL + h * HDIM;
#pragma unroll
    for (int pp = 0; pp < 2; pp++) {
        const float il0 = 1.f / lr[pp][0], il1 = 1.f / lr[pp][1];
        const int r0 = wr + pp * 16 + gid;
#pragma unroll
        for (int nt = 0; nt < 16; nt++) {
            const int col = nt * 8 + 2 * tig;
            *(__half2*)(og + (size_t)r0       * DMODEL + col) =
                __floats2half2_rn(Oc[pp][nt][0] * il0, Oc[pp][nt][1] * il0);
            *(__half2*)(og + (size_t)(r0 + 8) * DMODEL + col) =
                __floats2half2_rn(Oc[pp][nt][2] * il1, Oc[pp][nt][3] * il1);
        }
    }
}

// ---------------------------------------------------------------------------
// Projection: out[m][n] = sum_k g_attn[m][k] * Wh[n][k] + bc[n]  (fp16 mma)
// Tile 256(M) x 128(N), K-chunk 64 halves. 8 warps, warp owns 32 rows.
// (unchanged from the 505.9us kernel)
// ---------------------------------------------------------------------------
__global__ __launch_bounds__(256, 1)
void proj_kernel(const float* __restrict__ bc, float* __restrict__ out)
{
    extern __shared__ __half sh[];
    const uint32_t sbase = (uint32_t)__cvta_generic_to_shared(sh);

    const int tid  = threadIdx.x;
    const int warp = tid >> 5;
    const int lane = tid & 31;
    const int gid  = lane >> 2;
    const int tig  = lane & 3;
    const int n0 = blockIdx.x * PTN;
    const int m0 = blockIdx.y * PTM;
    const int wr = warp * 32;

    const __half* Ag = g_attn + (size_t)m0 * DMODEL;
    const __half* Bg = g_wh   + (size_t)n0 * DMODEL;

    auto issue_tile = [&](int j, int p) {
        const int kc = j * PTKC;
        const uint32_t aOff = sbase + (p ? POFF_A1 : POFF_A0) * 2;
        const uint32_t bOff = sbase + (p ? POFF_B1 : POFF_B0) * 2;
#pragma unroll
        for (int u = 0; u < 8; u++) {                      // A: 256 rows x 8 chunks
            int idx = tid + u * 256;
            int r = idx >> 3, c = idx & 7;
            int sub = c >> 2;
            CP16(aOff + (uint32_t)(sub * (PTM * 32) + r * 32 + (c & 3) * 8) * 2,
                 Ag + (size_t)r * DMODEL + kc + c * 8);
        }
#pragma unroll
        for (int u = 0; u < 4; u++) {                      // B: 128 rows x 8 chunks
            int idx = tid + u * 256;
            int r = idx >> 3, c = idx & 7;
            int sub = c >> 2;
            CP16(bOff + (uint32_t)(sub * (PTN * 32) + r * 32 + (c & 3) * 8) * 2,
                 Bg + (size_t)r * DMODEL + kc + c * 8);
        }
    };

    float acc[2][16][4];
#pragma unroll
    for (int p = 0; p < 2; p++)
#pragma unroll
        for (int i = 0; i < 16; i++) {
            acc[p][i][0] = acc[p][i][1] = acc[p][i][2] = acc[p][i][3] = 0.f;
        }

    issue_tile(0, 0);
    CPCOMMIT();

    const int NCH = DMODEL / PTKC;   // 32
    for (int j = 0; j < NCH; j++) {
        const int p = j & 1;
        if (j + 1 < NCH) issue_tile(j + 1, p ^ 1);
        CPCOMMIT();
        CPWAIT1();
        __syncthreads();

        const __half* As = sh + (p ? POFF_A1 : POFF_A0);
        const __half* Bs = sh + (p ? POFF_B1 : POFF_B0);

#pragma unroll
        for (int sub = 0; sub < 2; sub++) {
            const __half* Asub = As + sub * (PTM * 32);
            const __half* Bsub = Bs + sub * (PTN * 32);
            const int kk = 8 * tig;
            uint4 A0 = *(const uint4*)(Asub + (wr + gid)      * 32 + kk);
            uint4 A1 = *(const uint4*)(Asub + (wr + gid + 8)  * 32 + kk);
            uint4 A2 = *(const uint4*)(Asub + (wr + gid + 16) * 32 + kk);
            uint4 A3 = *(const uint4*)(Asub + (wr + gid + 24) * 32 + kk);
#pragma unroll
            for (int nt = 0; nt < 16; nt++) {
                uint4 B = *(const uint4*)(Bsub + (nt * 8 + gid) * 32 + kk);
                mma_f16(acc[0][nt], A0.x, A1.x, A0.y, A1.y, B.x, B.y);
                mma_f16(acc[0][nt], A0.z, A1.z, A0.w, A1.w, B.z, B.w);
                mma_f16(acc[1][nt], A2.x, A3.x, A2.y, A3.y, B.x, B.y);
                mma_f16(acc[1][nt], A2.z, A3.z, A2.w, A3.w, B.z, B.w);
            }
        }
        __syncthreads();
    }

    // Epilogue: bias + store
#pragma unroll
    for (int p = 0; p < 2; p++) {
        const int r0 = m0 + wr + p * 16 + gid;
#pragma unroll
        for (int nt = 0; nt < 16; nt++) {
            const int col = n0 + nt * 8 + 2 * tig;
            const float b0v = bc[col], b1v = bc[col + 1];
            float2 o0 = { acc[p][nt][0] + b0v, acc[p][nt][1] + b1v };
            float2 o1 = { acc[p][nt][2] + b0v, acc[p][nt][3] + b1v };
            *(float2*)(out + (size_t)r0       * DMODEL + col) = o0;
            *(float2*)(out + (size_t)(r0 + 8) * DMODEL + col) = o1;
        }
    }
}

// ---------------------------------------------------------------------------
extern "C" void kernel_launch(void* const* d_in, const int* in_sizes, int n_in,
                              void* d_out, int out_size)
{
    const float* q  = (const float*)d_in[0];
    const float* k  = (const float*)d_in[1];
    const float* v  = (const float*)d_in[2];
    const float* Wc = (const float*)d_in[3];
    const float* bc = (const float*)d_in[4];
    float* out = (float*)d_out;

    __half* kh_p; cudaGetSymbolAddress((void**)&kh_p, g_kh);
    __half* wh_p; cudaGetSymbolAddress((void**)&wh_p, g_wh);

    // Pre-passes: f32 -> f16 (K, Wc) and V transpose
    {
        int nk = BATCH * S_LEN * KVLD;
        conv_kernel<<<nk / 4 / 256, 256>>>(k, kh_p, nk);
        int nw = DMODEL * DMODEL;
        conv_kernel<<<nw / 4 / 256, 256>>>(Wc, wh_p, nw);
        dim3 tg(S_LEN / 32, HDIM / 32, BATCH * NG);
        vtrans_kernel<<<tg, dim3(32, 8)>>>(v);
    }

    cudaFuncSetAttribute(attn_kernel, cudaFuncAttributeMaxDynamicSharedMemorySize, ATTN_SMEM_BYTES);
    cudaFuncSetAttribute(proj_kernel, cudaFuncAttributeMaxDynamicSharedMemorySize, PROJ_SMEM_BYTES);

    dim3 agrid(S_LEN / BQ, NH, BATCH);
    attn_kernel<<<agrid, 128, ATTN_SMEM_BYTES>>>(q);

    dim3 pgrid(DMODEL / PTN, (BATCH * S_LEN) / PTM);
    proj_kernel<<<pgrid, 256, PROJ_SMEM_BYTES>>>(bc, out);
}

// round 10
// speedup vs baseline: 1.0672x; 1.0672x over previous
#include <cuda_runtime.h>
#include <cuda_fp16.h>
#include <math.h>
#include <stdint.h>

// Problem constants
#define S_LEN  2048
#define DMODEL 2048
#define HDIM   128
#define NH     16
#define NG     4
#define BATCH  2
#define KVLD   (NG * HDIM)   // 512

// Attention tiling: BQ=128 rows, 16 warps; warp pair = 16 Q rows, each warp
// half the n-range (QK: 32 of 64 cols, PV: 64 of 128 dims).
#define BQ    128
#define BK    64
#define NJT   (S_LEN / BK)   // 32
#define QPH   160            // Q/K smem pitch in halves (80 words ≡ 16 mod 32)
#define VPH   96             // Vt pitch in halves
#define PPH   96             // P  pitch in halves
// smem offsets (halves)
#define OFF_QS   0
#define OFF_KS0  (BQ * QPH)                 // 20480
#define OFF_KS1  (OFF_KS0 + BK * QPH)       // 30720
#define OFF_VT0  (OFF_KS1 + BK * QPH)       // 40960
#define OFF_VT1  (OFF_VT0 + HDIM * VPH)     // 53248
#define OFF_PS   (OFF_VT1 + HDIM * VPH)     // 65536
#define OFF_RED  (OFF_PS + BQ * PPH)        // 77824 (reduction floats start here)
#define ATTN_SMEM_BYTES  (OFF_RED * 2 + 2 * BQ * 2 * 4)   // + redmax/redsum

// Projection tiling: 256(M) x 128(N), K-chunk 64 halves (two 32-half subs)
#define PTM   256
#define PTN   128
#define PTKC  64
#define POFF_A0  0
#define POFF_A1  (PTM * PTKC)
#define POFF_B0  (2 * PTM * PTKC)
#define POFF_B1  (2 * PTM * PTKC + PTN * PTKC)
#define PROJ_SMEM_HALVES (2 * PTM * PTKC + 2 * PTN * PTKC)
#define PROJ_SMEM_BYTES  (PROJ_SMEM_HALVES * 2)

// fp16 globals
__device__ __half g_kh[(size_t)BATCH * S_LEN * KVLD];             // [b][s][g*128+d]
__device__ __half g_vt[(size_t)BATCH * NG * HDIM * S_LEN];        // [b][g][d][s]
__device__ __half g_wh[(size_t)DMODEL * DMODEL];                  // [n][k]
__device__ __half g_attn[(size_t)BATCH * S_LEN * DMODEL];         // [m][k]

__device__ __forceinline__ float ex2(float x) {
    float r; asm("ex2.approx.f32 %0, %1;" : "=f"(r) : "f"(x)); return r;
}

__device__ __forceinline__ void mma_f16(float c[4],
    uint32_t a0, uint32_t a1, uint32_t a2, uint32_t a3, uint32_t b0, uint32_t b1)
{
    asm volatile(
        "mma.sync.aligned.m16n8k16.row.col.f32.f16.f16.f32 "
        "{%0,%1,%2,%3}, {%4,%5,%6,%7}, {%8,%9}, {%0,%1,%2,%3};"
        : "+f"(c[0]), "+f"(c[1]), "+f"(c[2]), "+f"(c[3])
        : "r"(a0), "r"(a1), "r"(a2), "r"(a3), "r"(b0), "r"(b1));
}

#define CP16(dst, src) asm volatile( \
    "cp.async.cg.shared.global [%0], [%1], 16;" :: "r"(dst), "l"(src))
#define CPCOMMIT() asm volatile("cp.async.commit_group;")
#define CPWAIT1()  asm volatile("cp.async.wait_group 1;")

// ---------------------------------------------------------------------------
// Pre-pass: f32 -> f16 flat convert (n % 4 == 0)
// ---------------------------------------------------------------------------
__global__ void conv_kernel(const float* __restrict__ src, __half* __restrict__ dst, int n)
{
    int i = (blockIdx.x * blockDim.x + threadIdx.x) * 4;
    if (i < n) {
        float4 t = *(const float4*)(src + i);
        *(__half2*)(dst + i)     = __floats2half2_rn(t.x, t.y);
        *(__half2*)(dst + i + 2) = __floats2half2_rn(t.z, t.w);
    }
}

// Pre-pass: V transpose  v[b][s][g*128+d] -> g_vt[b][g][d][s], fp16
__global__ void vtrans_kernel(const float* __restrict__ v)
{
    __shared__ float t[32][33];
    const int b = blockIdx.z >> 2, g = blockIdx.z & 3;
    const int d0 = blockIdx.y * 32, s0 = blockIdx.x * 32;
    const int tx = threadIdx.x, ty = threadIdx.y;
#pragma unroll
    for (int i = 0; i < 32; i += 8)
        t[ty + i][tx] = v[(size_t)(b * S_LEN + s0 + ty + i) * KVLD + g * HDIM + d0 + tx];
    __syncthreads();
#pragma unroll
    for (int i = 0; i < 32; i += 8)
        g_vt[((size_t)(b * NG + g) * HDIM + d0 + ty + i) * S_LEN + s0 + tx] =
            __float2half_rn(t[tx][ty + i]);
}

// ---------------------------------------------------------------------------
// Flash attention, fp16 m16n8k16, online softmax (base-2), cp.async pipeline.
// Grid: (S/BQ, NH, B). Block 512 = 16 warps. Warp w: qpair = w>>1 owns Q rows
// [16*qpair, 16*qpair+16); side = w&1 splits the n-range.
// Pair max/sum combined through smem (redmax/redsum), so both warps of a pair
// hold identical m/l state.
// ---------------------------------------------------------------------------
__global__ __launch_bounds__(512, 1)
void attn_kernel(const float* __restrict__ q)
{
    extern __shared__ __half sh[];
    const uint32_t sbase = (uint32_t)__cvta_generic_to_shared(sh);
    float* redmax = (float*)(sh + OFF_RED);          // [128][2]
    float* redsum = redmax + 2 * BQ;                 // [128][2]

    const int tid  = threadIdx.x;
    const int warp = tid >> 5;
    const int lane = tid & 31;
    const int gid  = lane >> 2;
    const int tig  = lane & 3;
    const int qp   = warp >> 1;        // 0..7: 16-row strip
    const int side = warp & 1;         // n-half
    const int b  = blockIdx.z;
    const int h  = blockIdx.y;
    const int g  = h >> 2;
    const int s0 = blockIdx.x * BQ;
    const int wr = qp * 16;

    // scale * log2(e), folded into Q (softmax in base 2)
    const float scale = 0.08838834764831845f * 1.4426950408889634f;

    // Load + convert Q tile once (f32 -> f16, scaled)
    const float* qg = q + ((size_t)(b * S_LEN + s0)) * DMODEL + h * HDIM;
    for (int i = tid; i < BQ * (HDIM / 4); i += 512) {
        int r = i >> 5, c4 = (i & 31) << 2;
        float4 t = *(const float4*)(qg + (size_t)r * DMODEL + c4);
        __half* d = sh + OFF_QS + r * QPH + c4;
        *(__half2*)(d)     = __floats2half2_rn(t.x * scale, t.y * scale);
        *(__half2*)(d + 2) = __floats2half2_rn(t.z * scale, t.w * scale);
    }

    // cp.async source bases
    const __half* khb = g_kh + (size_t)b * S_LEN * KVLD + g * HDIM;
    const __half* vtb = g_vt + (size_t)(b * NG + g) * HDIM * S_LEN;

    // issue one tile's cp.asyncs into buffer p (512 threads, 2+2 chunks each)
    auto issue_tile = [&](int jt, int p) {
        const int kt0 = jt * BK;
        const uint32_t ksOff = sbase + (p ? OFF_KS1 : OFF_KS0) * 2;
        const uint32_t vtOff = sbase + (p ? OFF_VT1 : OFF_VT0) * 2;
#pragma unroll
        for (int u = 0; u < 2; u++) {
            int idx = tid + u * 512;
            int r = idx >> 4, c = idx & 15;                    // K: 64 rows x 16 chunks
            CP16(ksOff + (uint32_t)(r * QPH + c * 8) * 2,
                 khb + (size_t)(kt0 + r) * KVLD + c * 8);
        }
#pragma unroll
        for (int u = 0; u < 2; u++) {
            int idx = tid + u * 512;
            int d = idx >> 3, c = idx & 7;                     // V: 128 rows x 8 chunks
            CP16(vtOff + (uint32_t)(d * VPH + c * 8) * 2,
                 vtb + (size_t)d * S_LEN + kt0 + c * 8);
        }
    };

    issue_tile(0, 0);
    CPCOMMIT();

    // Per-warp state: 8 output n-tiles (this warp's 64 head dims)
    float Oc[8][4];
#pragma unroll
    for (int i = 0; i < 8; i++) { Oc[i][0] = Oc[i][1] = Oc[i][2] = Oc[i][3] = 0.f; }
    float m0r = -1e30f, m1r = -1e30f, l0 = 0.f, l1 = 0.f;

    const int row0 = wr + gid;          // this lane's first Q row
    const int row1 = wr + gid + 8;

    for (int jt = 0; jt < NJT; jt++) {
        const int p = jt & 1;
        if (jt + 1 < NJT) issue_tile(jt + 1, p ^ 1);
        CPCOMMIT();
        CPWAIT1();
        __syncthreads();   // tile jt ready for all warps

        const __half* Ks = sh + (p ? OFF_KS1 : OFF_KS0);
        const __half* Vt = sh + (p ? OFF_VT1 : OFF_VT0);
        __half* Ps = sh + OFF_PS;

        // ---- scores = Q @ K^T  (warp: 16 rows x 32 cols = its n-half) ----
        float sc[4][4];
#pragma unroll
        for (int i = 0; i < 4; i++) { sc[i][0] = sc[i][1] = sc[i][2] = sc[i][3] = 0.f; }

#pragma unroll
        for (int bi = 0; bi < 4; bi++) {
            const int kk = bi * 32 + 8 * tig;
            uint4 A0 = *(const uint4*)(sh + OFF_QS + row0 * QPH + kk);
            uint4 A1 = *(const uint4*)(sh + OFF_QS + row1 * QPH + kk);
#pragma unroll
            for (int ntl = 0; ntl < 4; ntl++) {
                const int nt = side * 4 + ntl;
                uint4 B = *(const uint4*)(Ks + (nt * 8 + gid) * QPH + kk);
                mma_f16(sc[ntl], A0.x, A1.x, A0.y, A1.y, B.x, B.y);
                mma_f16(sc[ntl], A0.z, A1.z, A0.w, A1.w, B.z, B.w);
            }
        }

        // ---- partial row max over this warp's 32 cols ----
        float mx0 = -1e30f, mx1 = -1e30f;
#pragma unroll
        for (int i = 0; i < 4; i++) {
            mx0 = fmaxf(mx0, fmaxf(sc[i][0], sc[i][1]));
            mx1 = fmaxf(mx1, fmaxf(sc[i][2], sc[i][3]));
        }
        mx0 = fmaxf(mx0, __shfl_xor_sync(0xffffffffu, mx0, 1));
        mx0 = fmaxf(mx0, __shfl_xor_sync(0xffffffffu, mx0, 2));
        mx1 = fmaxf(mx1, __shfl_xor_sync(0xffffffffu, mx1, 1));
        mx1 = fmaxf(mx1, __shfl_xor_sync(0xffffffffu, mx1, 2));
        if (tig == 0) {
            redmax[row0 * 2 + side] = mx0;
            redmax[row1 * 2 + side] = mx1;
        }
        __syncthreads();

        // combined max across the pair
        mx0 = fmaxf(redmax[row0 * 2], redmax[row0 * 2 + 1]);
        mx1 = fmaxf(redmax[row1 * 2], redmax[row1 * 2 + 1]);
        const float mn0 = fmaxf(m0r, mx0), mn1 = fmaxf(m1r, mx1);
        const float al0 = ex2(m0r - mn0), al1 = ex2(m1r - mn1);
        m0r = mn0; m1r = mn1;

        // ---- exp, partial sum, write P (this warp's 32 cols) ----
        float s0s = 0.f, s1s = 0.f;
#pragma unroll
        for (int ntl = 0; ntl < 4; ntl++) {
            const int nt = side * 4 + ntl;
            float p0 = ex2(sc[ntl][0] - mn0);
            float p1 = ex2(sc[ntl][1] - mn0);
            float p2 = ex2(sc[ntl][2] - mn1);
            float p3 = ex2(sc[ntl][3] - mn1);
            s0s += p0 + p1; s1s += p2 + p3;
            *(__half2*)(Ps + row0 * PPH + nt * 8 + 2 * tig) = __floats2half2_rn(p0, p1);
            *(__half2*)(Ps + row1 * PPH + nt * 8 + 2 * tig) = __floats2half2_rn(p2, p3);
        }
        s0s += __shfl_xor_sync(0xffffffffu, s0s, 1);
        s0s += __shfl_xor_sync(0xffffffffu, s0s, 2);
        s1s += __shfl_xor_sync(0xffffffffu, s1s, 1);
        s1s += __shfl_xor_sync(0xffffffffu, s1s, 2);
        if (tig == 0) {
            redsum[row0 * 2 + side] = s0s;
            redsum[row1 * 2 + side] = s1s;
        }

        // rescale O while the other warp finishes
#pragma unroll
        for (int nt = 0; nt < 8; nt++) {
            Oc[nt][0] *= al0; Oc[nt][1] *= al0;
            Oc[nt][2] *= al1; Oc[nt][3] *= al1;
        }
        __syncthreads();   // P tile + partial sums visible

        l0 = l0 * al0 + redsum[row0 * 2] + redsum[row0 * 2 + 1];
        l1 = l1 * al1 + redsum[row1 * 2] + redsum[row1 * 2 + 1];

        // ---- O += P @ V  (warp: 16 rows x its 64 head dims) ----
#pragma unroll
        for (int bi = 0; bi < 2; bi++) {
            const int kk = bi * 32 + 8 * tig;
            uint4 A0 = *(const uint4*)(Ps + row0 * PPH + kk);
            uint4 A1 = *(const uint4*)(Ps + row1 * PPH + kk);
#pragma unroll
            for (int ntl = 0; ntl < 8; ntl++) {
                const int d = side * 64 + ntl * 8 + gid;
                uint4 B = *(const uint4*)(Vt + d * VPH + kk);
                mma_f16(Oc[ntl], A0.x, A1.x, A0.y, A1.y, B.x, B.y);
                mma_f16(Oc[ntl], A0.z, A1.z, A0.w, A1.w, B.z, B.w);
            }
        }
        __syncthreads();   // all warps done with buffer p (and Ps) before refill
    }

    // Epilogue: normalize, convert to fp16, store this warp's 64 dims
    const float il0 = 1.f / l0, il1 = 1.f / l1;
    __half* og = g_attn + (size_t)(b * S_LEN + s0) * DMODEL + h * HDIM + side * 64;
#pragma unroll
    for (int nt = 0; nt < 8; nt++) {
        const int col = nt * 8 + 2 * tig;
        *(__half2*)(og + (size_t)row0 * DMODEL + col) =
            __floats2half2_rn(Oc[nt][0] * il0, Oc[nt][1] * il0);
        *(__half2*)(og + (size_t)row1 * DMODEL + col) =
            __floats2half2_rn(Oc[nt][2] * il1, Oc[nt][3] * il1);
    }
}

// ---------------------------------------------------------------------------
// Projection: out[m][n] = sum_k g_attn[m][k] * Wh[n][k] + bc[n]  (fp16 mma)
// Tile 256(M) x 128(N), K-chunk 64 halves. 8 warps, warp owns 32 rows.
// (unchanged from the 505.9us kernel)
// ---------------------------------------------------------------------------
__global__ __launch_bounds__(256, 1)
void proj_kernel(const float* __restrict__ bc, float* __restrict__ out)
{
    extern __shared__ __half sh[];
    const uint32_t sbase = (uint32_t)__cvta_generic_to_shared(sh);

    const int tid  = threadIdx.x;
    const int warp = tid >> 5;
    const int lane = tid & 31;
    const int gid  = lane >> 2;
    const int tig  = lane & 3;
    const int n0 = blockIdx.x * PTN;
    const int m0 = blockIdx.y * PTM;
    const int wr = warp * 32;

    const __half* Ag = g_attn + (size_t)m0 * DMODEL;
    const __half* Bg = g_wh   + (size_t)n0 * DMODEL;

    auto issue_tile = [&](int j, int p) {
        const int kc = j * PTKC;
        const uint32_t aOff = sbase + (p ? POFF_A1 : POFF_A0) * 2;
        const uint32_t bOff = sbase + (p ? POFF_B1 : POFF_B0) * 2;
#pragma unroll
        for (int u = 0; u < 8; u++) {                      // A: 256 rows x 8 chunks
            int idx = tid + u * 256;
            int r = idx >> 3, c = idx & 7;
            int sub = c >> 2;
            CP16(aOff + (uint32_t)(sub * (PTM * 32) + r * 32 + (c & 3) * 8) * 2,
                 Ag + (size_t)r * DMODEL + kc + c * 8);
        }
#pragma unroll
        for (int u = 0; u < 4; u++) {                      // B: 128 rows x 8 chunks
            int idx = tid + u * 256;
            int r = idx >> 3, c = idx & 7;
            int sub = c >> 2;
            CP16(bOff + (uint32_t)(sub * (PTN * 32) + r * 32 + (c & 3) * 8) * 2,
                 Bg + (size_t)r * DMODEL + kc + c * 8);
        }
    };

    float acc[2][16][4];
#pragma unroll
    for (int p = 0; p < 2; p++)
#pragma unroll
        for (int i = 0; i < 16; i++) {
            acc[p][i][0] = acc[p][i][1] = acc[p][i][2] = acc[p][i][3] = 0.f;
        }

    issue_tile(0, 0);
    CPCOMMIT();

    const int NCH = DMODEL / PTKC;   // 32
    for (int j = 0; j < NCH; j++) {
        const int p = j & 1;
        if (j + 1 < NCH) issue_tile(j + 1, p ^ 1);
        CPCOMMIT();
        CPWAIT1();
        __syncthreads();

        const __half* As = sh + (p ? POFF_A1 : POFF_A0);
        const __half* Bs = sh + (p ? POFF_B1 : POFF_B0);

#pragma unroll
        for (int sub = 0; sub < 2; sub++) {
            const __half* Asub = As + sub * (PTM * 32);
            const __half* Bsub = Bs + sub * (PTN * 32);
            const int kk = 8 * tig;
            uint4 A0 = *(const uint4*)(Asub + (wr + gid)      * 32 + kk);
            uint4 A1 = *(const uint4*)(Asub + (wr + gid + 8)  * 32 + kk);
            uint4 A2 = *(const uint4*)(Asub + (wr + gid + 16) * 32 + kk);
            uint4 A3 = *(const uint4*)(Asub + (wr + gid + 24) * 32 + kk);
#pragma unroll
            for (int nt = 0; nt < 16; nt++) {
                uint4 B = *(const uint4*)(Bsub + (nt * 8 + gid) * 32 + kk);
                mma_f16(acc[0][nt], A0.x, A1.x, A0.y, A1.y, B.x, B.y);
                mma_f16(acc[0][nt], A0.z, A1.z, A0.w, A1.w, B.z, B.w);
                mma_f16(acc[1][nt], A2.x, A3.x, A2.y, A3.y, B.x, B.y);
                mma_f16(acc[1][nt], A2.z, A3.z, A2.w, A3.w, B.z, B.w);
            }
        }
        __syncthreads();
    }

    // Epilogue: bias + store
#pragma unroll
    for (int p = 0; p < 2; p++) {
        const int r0 = m0 + wr + p * 16 + gid;
#pragma unroll
        for (int nt = 0; nt < 16; nt++) {
            const int col = n0 + nt * 8 + 2 * tig;
            const float b0v = bc[col], b1v = bc[col + 1];
            float2 o0 = { acc[p][nt][0] + b0v, acc[p][nt][1] + b1v };
            float2 o1 = { acc[p][nt][2] + b0v, acc[p][nt][3] + b1v };
            *(float2*)(out + (size_t)r0       * DMODEL + col) = o0;
            *(float2*)(out + (size_t)(r0 + 8) * DMODEL + col) = o1;
        }
    }
}

// ---------------------------------------------------------------------------
extern "C" void kernel_launch(void* const* d_in, const int* in_sizes, int n_in,
                              void* d_out, int out_size)
{
    const float* q  = (const float*)d_in[0];
    const float* k  = (const float*)d_in[1];
    const float* v  = (const float*)d_in[2];
    const float* Wc = (const float*)d_in[3];
    const float* bc = (const float*)d_in[4];
    float* out = (float*)d_out;

    __half* kh_p; cudaGetSymbolAddress((void**)&kh_p, g_kh);
    __half* wh_p; cudaGetSymbolAddress((void**)&wh_p, g_wh);

    // Pre-passes: f32 -> f16 (K, Wc) and V transpose
    {
        int nk = BATCH * S_LEN * KVLD;
        conv_kernel<<<nk / 4 / 256, 256>>>(k, kh_p, nk);
        int nw = DMODEL * DMODEL;
        conv_kernel<<<nw / 4 / 256, 256>>>(Wc, wh_p, nw);
        dim3 tg(S_LEN / 32, HDIM / 32, BATCH * NG);
        vtrans_kernel<<<tg, dim3(32, 8)>>>(v);
    }

    cudaFuncSetAttribute(attn_kernel, cudaFuncAttributeMaxDynamicSharedMemorySize, ATTN_SMEM_BYTES);
    cudaFuncSetAttribute(proj_kernel, cudaFuncAttributeMaxDynamicSharedMemorySize, PROJ_SMEM_BYTES);

    dim3 agrid(S_LEN / BQ, NH, BATCH);
    attn_kernel<<<agrid, 512, ATTN_SMEM_BYTES>>>(q);

    dim3 pgrid(DMODEL / PTN, (BATCH * S_LEN) / PTM);
    proj_kernel<<<pgrid, 256, PROJ_SMEM_BYTES>>>(bc, out);
}

// round 11
// speedup vs baseline: 1.2378x; 1.1599x over previous
#include <cuda_runtime.h>
#include <cuda_fp16.h>
#include <math.h>
#include <stdint.h>

// Problem constants
#define S_LEN  2048
#define DMODEL 2048
#define HDIM   128
#define NH     16
#define NG     4
#define BATCH  2
#define KVLD   (NG * HDIM)   // 512

// Attention tiling: BQ=128, 8 warps x 16 rows, BK=64, double-buffered K/V.
// All tiles stored as [sub(32 halves of k)][row][32] contiguous -> zero padding,
// conflict-free LDS.128 (pitch 16 words), smem 112KB -> 2 CTAs/SM.
#define BQ    128
#define BK    64
#define NJT   (S_LEN / BK)   // 32
// smem offsets (halves)
#define OFF_QS   0                          // [4][128][32] = 16384
#define OFF_KS0  16384                      // [4][64][32]  = 8192
#define OFF_KS1  24576
#define OFF_VT0  32768                      // [2][128][32] = 8192
#define OFF_VT1  40960
#define OFF_PS   49152                      // [2][128][32] = 8192
#define ATTN_SMEM_HALVES 57344
#define ATTN_SMEM_BYTES  (ATTN_SMEM_HALVES * 2)   // 114688 B = 112 KB

// Projection tiling: 256(M) x 128(N), K-chunk 64 halves (two 32-half subs)
#define PTM   256
#define PTN   128
#define PTKC  64
#define POFF_A0  0
#define POFF_A1  (PTM * PTKC)
#define POFF_B0  (2 * PTM * PTKC)
#define POFF_B1  (2 * PTM * PTKC + PTN * PTKC)
#define PROJ_SMEM_HALVES (2 * PTM * PTKC + 2 * PTN * PTKC)
#define PROJ_SMEM_BYTES  (PROJ_SMEM_HALVES * 2)

// fp16 globals
__device__ __half g_kh[(size_t)BATCH * S_LEN * KVLD];             // [b][s][g*128+d]
__device__ __half g_vt[(size_t)BATCH * NG * HDIM * S_LEN];        // [b][g][d][s]
__device__ __half g_wh[(size_t)DMODEL * DMODEL];                  // [n][k]
__device__ __half g_attn[(size_t)BATCH * S_LEN * DMODEL];         // [m][k]

__device__ __forceinline__ float ex2(float x) {
    float r; asm("ex2.approx.f32 %0, %1;" : "=f"(r) : "f"(x)); return r;
}

__device__ __forceinline__ void mma_f16(float c[4],
    uint32_t a0, uint32_t a1, uint32_t a2, uint32_t a3, uint32_t b0, uint32_t b1)
{
    asm volatile(
        "mma.sync.aligned.m16n8k16.row.col.f32.f16.f16.f32 "
        "{%0,%1,%2,%3}, {%4,%5,%6,%7}, {%8,%9}, {%0,%1,%2,%3};"
        : "+f"(c[0]), "+f"(c[1]), "+f"(c[2]), "+f"(c[3])
        : "r"(a0), "r"(a1), "r"(a2), "r"(a3), "r"(b0), "r"(b1));
}

#define CP16(dst, src) asm volatile( \
    "cp.async.cg.shared.global [%0], [%1], 16;" :: "r"(dst), "l"(src))
#define CPCOMMIT() asm volatile("cp.async.commit_group;")
#define CPWAIT1()  asm volatile("cp.async.wait_group 1;")

// ---------------------------------------------------------------------------
// Pre-pass: f32 -> f16 flat convert (n % 4 == 0)
// ---------------------------------------------------------------------------
__global__ void conv_kernel(const float* __restrict__ src, __half* __restrict__ dst, int n)
{
    int i = (blockIdx.x * blockDim.x + threadIdx.x) * 4;
    if (i < n) {
        float4 t = *(const float4*)(src + i);
        *(__half2*)(dst + i)     = __floats2half2_rn(t.x, t.y);
        *(__half2*)(dst + i + 2) = __floats2half2_rn(t.z, t.w);
    }
}

// Pre-pass: V transpose  v[b][s][g*128+d] -> g_vt[b][g][d][s], fp16
__global__ void vtrans_kernel(const float* __restrict__ v)
{
    __shared__ float t[32][33];
    const int b = blockIdx.z >> 2, g = blockIdx.z & 3;
    const int d0 = blockIdx.y * 32, s0 = blockIdx.x * 32;
    const int tx = threadIdx.x, ty = threadIdx.y;
#pragma unroll
    for (int i = 0; i < 32; i += 8)
        t[ty + i][tx] = v[(size_t)(b * S_LEN + s0 + ty + i) * KVLD + g * HDIM + d0 + tx];
    __syncthreads();
#pragma unroll
    for (int i = 0; i < 32; i += 8)
        g_vt[((size_t)(b * NG + g) * HDIM + d0 + ty + i) * S_LEN + s0 + tx] =
            __float2half_rn(t[tx][ty + i]);
}

// ---------------------------------------------------------------------------
// Flash attention, fp16 m16n8k16, online softmax (base-2), cp.async pipeline.
// Grid: (S/BQ, NH, B). Block 256 = 8 warps x 16 Q rows. 2 CTAs/SM.
// Sub-block smem layout: tile[(c/32)*ROWS + row][c%32] -> pitch 16 words,
// conflict-free LDS.128 without padding.
// ---------------------------------------------------------------------------
__global__ __launch_bounds__(256, 2)
void attn_kernel(const float* __restrict__ q)
{
    extern __shared__ __half sh[];
    const uint32_t sbase = (uint32_t)__cvta_generic_to_shared(sh);

    const int tid  = threadIdx.x;
    const int warp = tid >> 5;
    const int lane = tid & 31;
    const int gid  = lane >> 2;
    const int tig  = lane & 3;
    const int b  = blockIdx.z;
    const int h  = blockIdx.y;
    const int g  = h >> 2;
    const int s0 = blockIdx.x * BQ;
    const int wr = warp * 16;

    // scale * log2(e), folded into Q (softmax in base 2)
    const float scale = 0.08838834764831845f * 1.4426950408889634f;

    // Load + convert Q tile once (f32 -> f16, scaled), sub-block layout
    const float* qg = q + ((size_t)(b * S_LEN + s0)) * DMODEL + h * HDIM;
    for (int i = tid; i < BQ * (HDIM / 4); i += 256) {
        int r = i >> 5, c4 = (i & 31) << 2;       // 4-half chunk at col c4
        float4 t = *(const float4*)(qg + (size_t)r * DMODEL + c4);
        __half* d = sh + OFF_QS + ((c4 >> 5) * BQ + r) * 32 + (c4 & 31);
        *(__half2*)(d)     = __floats2half2_rn(t.x * scale, t.y * scale);
        *(__half2*)(d + 2) = __floats2half2_rn(t.z * scale, t.w * scale);
    }

    // cp.async source bases
    const __half* khb = g_kh + (size_t)b * S_LEN * KVLD + g * HDIM;
    const __half* vtb = g_vt + (size_t)(b * NG + g) * HDIM * S_LEN;

    // issue one tile's cp.asyncs into buffer p (256 threads, 4+4 chunks each)
    auto issue_tile = [&](int jt, int p) {
        const int kt0 = jt * BK;
        const uint32_t ksOff = sbase + (p ? OFF_KS1 : OFF_KS0) * 2;
        const uint32_t vtOff = sbase + (p ? OFF_VT1 : OFF_VT0) * 2;
#pragma unroll
        for (int u = 0; u < 4; u++) {
            int idx = tid + u * 256;
            int r = idx >> 4, c = idx & 15;        // K: 64 rows x 16 chunks
            CP16(ksOff + (uint32_t)(((c >> 2) * BK + r) * 32 + (c & 3) * 8) * 2,
                 khb + (size_t)(kt0 + r) * KVLD + c * 8);
        }
#pragma unroll
        for (int u = 0; u < 4; u++) {
            int idx = tid + u * 256;
            int d = idx >> 3, c = idx & 7;         // V: 128 rows x 8 chunks
            CP16(vtOff + (uint32_t)(((c >> 2) * HDIM + d) * 32 + (c & 3) * 8) * 2,
                 vtb + (size_t)d * S_LEN + kt0 + c * 8);
        }
    };

    issue_tile(0, 0);
    CPCOMMIT();

    float Oc[16][4];
#pragma unroll
    for (int i = 0; i < 16; i++) { Oc[i][0] = Oc[i][1] = Oc[i][2] = Oc[i][3] = 0.f; }
    float m0r = -1e30f, m1r = -1e30f, l0 = 0.f, l1 = 0.f;

    const int row0 = wr + gid;
    const int row1 = wr + gid + 8;

    for (int jt = 0; jt < NJT; jt++) {
        const int p = jt & 1;
        if (jt + 1 < NJT) issue_tile(jt + 1, p ^ 1);
        CPCOMMIT();
        CPWAIT1();
        __syncthreads();   // tile jt ready for all warps

        const __half* Ks = sh + (p ? OFF_KS1 : OFF_KS0);
        const __half* Vt = sh + (p ? OFF_VT1 : OFF_VT0);
        __half* Ps = sh + OFF_PS;

        // ---- scores = Q @ K^T  (warp: 16 x 64) ----
        float sc[8][4];
#pragma unroll
        for (int i = 0; i < 8; i++) { sc[i][0] = sc[i][1] = sc[i][2] = sc[i][3] = 0.f; }

#pragma unroll
        for (int bi = 0; bi < 4; bi++) {
            uint4 A0 = *(const uint4*)(sh + OFF_QS + ((bi * BQ + row0) * 32 + 8 * tig));
            uint4 A1 = *(const uint4*)(sh + OFF_QS + ((bi * BQ + row1) * 32 + 8 * tig));
#pragma unroll
            for (int nt = 0; nt < 8; nt++) {
                uint4 B = *(const uint4*)(Ks + ((bi * BK + nt * 8 + gid) * 32 + 8 * tig));
                mma_f16(sc[nt], A0.x, A1.x, A0.y, A1.y, B.x, B.y);
                mma_f16(sc[nt], A0.z, A1.z, A0.w, A1.w, B.z, B.w);
            }
        }

        // ---- online softmax (base 2) ----
        float mx0 = -1e30f, mx1 = -1e30f;
#pragma unroll
        for (int nt = 0; nt < 8; nt++) {
            mx0 = fmaxf(mx0, fmaxf(sc[nt][0], sc[nt][1]));
            mx1 = fmaxf(mx1, fmaxf(sc[nt][2], sc[nt][3]));
        }
        mx0 = fmaxf(mx0, __shfl_xor_sync(0xffffffffu, mx0, 1));
        mx0 = fmaxf(mx0, __shfl_xor_sync(0xffffffffu, mx0, 2));
        mx1 = fmaxf(mx1, __shfl_xor_sync(0xffffffffu, mx1, 1));
        mx1 = fmaxf(mx1, __shfl_xor_sync(0xffffffffu, mx1, 2));
        const float mn0 = fmaxf(m0r, mx0), mn1 = fmaxf(m1r, mx1);
        const float al0 = ex2(m0r - mn0), al1 = ex2(m1r - mn1);
        m0r = mn0; m1r = mn1;

        float s0s = 0.f, s1s = 0.f;
#pragma unroll
        for (int nt = 0; nt < 8; nt++) {
            float p0 = ex2(sc[nt][0] - mn0);
            float p1 = ex2(sc[nt][1] - mn0);
            float p2 = ex2(sc[nt][2] - mn1);
            float p3 = ex2(sc[nt][3] - mn1);
            s0s += p0 + p1; s1s += p2 + p3;
            // P sub-block addr: col = nt*8 + 2*tig -> sub = nt>>2, within = (nt&3)*8 + 2*tig
            __half* d0 = Ps + (((nt >> 2) * BQ + row0) * 32 + (nt & 3) * 8 + 2 * tig);
            __half* d1 = Ps + (((nt >> 2) * BQ + row1) * 32 + (nt & 3) * 8 + 2 * tig);
            *(__half2*)d0 = __floats2half2_rn(p0, p1);
            *(__half2*)d1 = __floats2half2_rn(p2, p3);
        }
        s0s += __shfl_xor_sync(0xffffffffu, s0s, 1);
        s0s += __shfl_xor_sync(0xffffffffu, s0s, 2);
        s1s += __shfl_xor_sync(0xffffffffu, s1s, 1);
        s1s += __shfl_xor_sync(0xffffffffu, s1s, 2);
        l0 = l0 * al0 + s0s;
        l1 = l1 * al1 + s1s;

#pragma unroll
        for (int nt = 0; nt < 16; nt++) {
            Oc[nt][0] *= al0; Oc[nt][1] *= al0;
            Oc[nt][2] *= al1; Oc[nt][3] *= al1;
        }
        __syncwarp();   // Ps rows are warp-private

        // ---- O += P @ V  (warp: 16 x 128) ----
#pragma unroll
        for (int bi = 0; bi < 2; bi++) {
            uint4 A0 = *(const uint4*)(Ps + ((bi * BQ + row0) * 32 + 8 * tig));
            uint4 A1 = *(const uint4*)(Ps + ((bi * BQ + row1) * 32 + 8 * tig));
#pragma unroll
            for (int nt = 0; nt < 16; nt++) {
                uint4 B = *(const uint4*)(Vt + ((bi * HDIM + nt * 8 + gid) * 32 + 8 * tig));
                mma_f16(Oc[nt], A0.x, A1.x, A0.y, A1.y, B.x, B.y);
                mma_f16(Oc[nt], A0.z, A1.z, A0.w, A1.w, B.z, B.w);
            }
        }
        __syncthreads();   // all warps done with buffer p before refill
    }

    // Epilogue: normalize, convert to fp16, store to g_attn
    const float il0 = 1.f / l0, il1 = 1.f / l1;
    __half* og = g_attn + (size_t)(b * S_LEN + s0) * DMODEL + h * HDIM;
#pragma unroll
    for (int nt = 0; nt < 16; nt++) {
        const int col = nt * 8 + 2 * tig;
        *(__half2*)(og + (size_t)row0 * DMODEL + col) =
            __floats2half2_rn(Oc[nt][0] * il0, Oc[nt][1] * il0);
        *(__half2*)(og + (size_t)row1 * DMODEL + col) =
            __floats2half2_rn(Oc[nt][2] * il1, Oc[nt][3] * il1);
    }
}

// ---------------------------------------------------------------------------
// Projection: out[m][n] = sum_k g_attn[m][k] * Wh[n][k] + bc[n]  (fp16 mma)
// Tile 256(M) x 128(N), K-chunk 64 halves. 8 warps, warp owns 32 rows.
// (unchanged from the 505.9us kernel)
// ---------------------------------------------------------------------------
__global__ __launch_bounds__(256, 1)
void proj_kernel(const float* __restrict__ bc, float* __restrict__ out)
{
    extern __shared__ __half sh[];
    const uint32_t sbase = (uint32_t)__cvta_generic_to_shared(sh);

    const int tid  = threadIdx.x;
    const int warp = tid >> 5;
    const int lane = tid & 31;
    const int gid  = lane >> 2;
    const int tig  = lane & 3;
    const int n0 = blockIdx.x * PTN;
    const int m0 = blockIdx.y * PTM;
    const int wr = warp * 32;

    const __half* Ag = g_attn + (size_t)m0 * DMODEL;
    const __half* Bg = g_wh   + (size_t)n0 * DMODEL;

    auto issue_tile = [&](int j, int p) {
        const int kc = j * PTKC;
        const uint32_t aOff = sbase + (p ? POFF_A1 : POFF_A0) * 2;
        const uint32_t bOff = sbase + (p ? POFF_B1 : POFF_B0) * 2;
#pragma unroll
        for (int u = 0; u < 8; u++) {                      // A: 256 rows x 8 chunks
            int idx = tid + u * 256;
            int r = idx >> 3, c = idx & 7;
            int sub = c >> 2;
            CP16(aOff + (uint32_t)(sub * (PTM * 32) + r * 32 + (c & 3) * 8) * 2,
                 Ag + (size_t)r * DMODEL + kc + c * 8);
        }
#pragma unroll
        for (int u = 0; u < 4; u++) {                      // B: 128 rows x 8 chunks
            int idx = tid + u * 256;
            int r = idx >> 3, c = idx & 7;
            int sub = c >> 2;
            CP16(bOff + (uint32_t)(sub * (PTN * 32) + r * 32 + (c & 3) * 8) * 2,
                 Bg + (size_t)r * DMODEL + kc + c * 8);
        }
    };

    float acc[2][16][4];
#pragma unroll
    for (int p = 0; p < 2; p++)
#pragma unroll
        for (int i = 0; i < 16; i++) {
            acc[p][i][0] = acc[p][i][1] = acc[p][i][2] = acc[p][i][3] = 0.f;
        }

    issue_tile(0, 0);
    CPCOMMIT();

    const int NCH = DMODEL / PTKC;   // 32
    for (int j = 0; j < NCH; j++) {
        const int p = j & 1;
        if (j + 1 < NCH) issue_tile(j + 1, p ^ 1);
        CPCOMMIT();
        CPWAIT1();
        __syncthreads();

        const __half* As = sh + (p ? POFF_A1 : POFF_A0);
        const __half* Bs = sh + (p ? POFF_B1 : POFF_B0);

#pragma unroll
        for (int sub = 0; sub < 2; sub++) {
            const __half* Asub = As + sub * (PTM * 32);
            const __half* Bsub = Bs + sub * (PTN * 32);
            const int kk = 8 * tig;
            uint4 A0 = *(const uint4*)(Asub + (wr + gid)      * 32 + kk);
            uint4 A1 = *(const uint4*)(Asub + (wr + gid + 8)  * 32 + kk);
            uint4 A2 = *(const uint4*)(Asub + (wr + gid + 16) * 32 + kk);
            uint4 A3 = *(const uint4*)(Asub + (wr + gid + 24) * 32 + kk);
#pragma unroll
            for (int nt = 0; nt < 16; nt++) {
                uint4 B = *(const uint4*)(Bsub + (nt * 8 + gid) * 32 + kk);
                mma_f16(acc[0][nt], A0.x, A1.x, A0.y, A1.y, B.x, B.y);
                mma_f16(acc[0][nt], A0.z, A1.z, A0.w, A1.w, B.z, B.w);
                mma_f16(acc[1][nt], A2.x, A3.x, A2.y, A3.y, B.x, B.y);
                mma_f16(acc[1][nt], A2.z, A3.z, A2.w, A3.w, B.z, B.w);
            }
        }
        __syncthreads();
    }

    // Epilogue: bias + store
#pragma unroll
    for (int p = 0; p < 2; p++) {
        const int r0 = m0 + wr + p * 16 + gid;
#pragma unroll
        for (int nt = 0; nt < 16; nt++) {
            const int col = n0 + nt * 8 + 2 * tig;
            const float b0v = bc[col], b1v = bc[col + 1];
            float2 o0 = { acc[p][nt][0] + b0v, acc[p][nt][1] + b1v };
            float2 o1 = { acc[p][nt][2] + b0v, acc[p][nt][3] + b1v };
            *(float2*)(out + (size_t)r0       * DMODEL + col) = o0;
            *(float2*)(out + (size_t)(r0 + 8) * DMODEL + col) = o1;
        }
    }
}

// ---------------------------------------------------------------------------
extern "C" void kernel_launch(void* const* d_in, const int* in_sizes, int n_in,
                              void* d_out, int out_size)
{
    const float* q  = (const float*)d_in[0];
    const float* k  = (const float*)d_in[1];
    const float* v  = (const float*)d_in[2];
    const float* Wc = (const float*)d_in[3];
    const float* bc = (const float*)d_in[4];
    float* out = (float*)d_out;

    __half* kh_p; cudaGetSymbolAddress((void**)&kh_p, g_kh);
    __half* wh_p; cudaGetSymbolAddress((void**)&wh_p, g_wh);

    // Pre-passes: f32 -> f16 (K, Wc) and V transpose
    {
        int nk = BATCH * S_LEN * KVLD;
        conv_kernel<<<nk / 4 / 256, 256>>>(k, kh_p, nk);
        int nw = DMODEL * DMODEL;
        conv_kernel<<<nw / 4 / 256, 256>>>(Wc, wh_p, nw);
        dim3 tg(S_LEN / 32, HDIM / 32, BATCH * NG);
        vtrans_kernel<<<tg, dim3(32, 8)>>>(v);
    }

    cudaFuncSetAttribute(attn_kernel, cudaFuncAttributeMaxDynamicSharedMemorySize, ATTN_SMEM_BYTES);
    cudaFuncSetAttribute(proj_kernel, cudaFuncAttributeMaxDynamicSharedMemorySize, PROJ_SMEM_BYTES);

    dim3 agrid(S_LEN / BQ, NH, BATCH);
    attn_kernel<<<agrid, 256, ATTN_SMEM_BYTES>>>(q);

    dim3 pgrid(DMODEL / PTN, (BATCH * S_LEN) / PTM);
    proj_kernel<<<pgrid, 256, PROJ_SMEM_BYTES>>>(bc, out);
}